// round 14
// baseline (speedup 1.0000x reference)
#include <cuda_runtime.h>
#include <cuda_bf16.h>
#include <cuda_fp16.h>
#include <cstddef>
#include <cstdint>

#define BATCH 16
#define SEQ   1024
#define DIM   768
#define NHEAD 12
#define DHEAD 64
#define INNER 768            // NHEAD*DHEAD
#define QK_SCALE 0.125f      // DHEAD^-0.5
#define MTOT (BATCH * SEQ)   // 16384

// ---------------- scratch (device globals; no allocation allowed) ----------------
__device__ float g_kv[(size_t)MTOT * 2 * INNER];                    // 101 MB (V half used)
__device__ float g_at[(size_t)BATCH * NHEAD * SEQ * SEQ];           // 805 MB
#define QK_ELEMS ((size_t)BATCH * NHEAD * SEQ * DHEAD)              // 12.58M
#define X_ELEMS  ((size_t)MTOT * INNER)                             // 12.58M
// bf16 splits
__device__ __nv_bfloat16 g_xh[X_ELEMS], g_xl[X_ELEMS];
__device__ __nv_bfloat16 g_oh[X_ELEMS], g_ol[X_ELEMS];
__device__ __nv_bfloat16 g_qh[QK_ELEMS], g_ql[QK_ELEMS];
__device__ __nv_bfloat16 g_kh[QK_ELEMS], g_kl[QK_ELEMS];
// V transposed+split [b,h,d,j]  (fp16 for the 2-pass AV)
__device__ __half g_vth[QK_ELEMS], g_vtl[QK_ELEMS];
// transposed+split weights [N][K]
__device__ __nv_bfloat16 g_wqt_h[DIM * INNER], g_wqt_l[DIM * INNER];
__device__ __nv_bfloat16 g_wkt_h[DIM * INNER], g_wkt_l[DIM * INNER];
__device__ __nv_bfloat16 g_wvt_h[DIM * INNER], g_wvt_l[DIM * INNER];
__device__ __nv_bfloat16 g_wot_h[INNER * DIM], g_wot_l[INNER * DIM];

// ---------------- cp.async helpers ----------------
__device__ __forceinline__ void cp16(uint32_t saddr, const void* gptr) {
    asm volatile("cp.async.cg.shared.global [%0], [%1], 16;" :: "r"(saddr), "l"(gptr));
}
__device__ __forceinline__ void cp_commit() { asm volatile("cp.async.commit_group;"); }
__device__ __forceinline__ void cp_wait0()  { asm volatile("cp.async.wait_group 0;"); }
__device__ __forceinline__ void cp_wait1()  { asm volatile("cp.async.wait_group 1;"); }

// ---------------- mma.sync / ldmatrix helpers (baseline PTX) ----------------
__device__ __forceinline__ uint32_t smem_to_u32(const void* p) {
    uint32_t a;
    asm("{ .reg .u64 t; cvta.to.shared.u64 t, %1; cvt.u32.u64 %0, t; }" : "=r"(a) : "l"(p));
    return a;
}
__device__ __forceinline__ void ldsm_x4(uint32_t* r, uint32_t addr) {
    asm volatile("ldmatrix.sync.aligned.m8n8.x4.shared.b16 {%0,%1,%2,%3}, [%4];"
        : "=r"(r[0]), "=r"(r[1]), "=r"(r[2]), "=r"(r[3]) : "r"(addr));
}
__device__ __forceinline__ void ldsm_x2(uint32_t* r, uint32_t addr) {
    asm volatile("ldmatrix.sync.aligned.m8n8.x2.shared.b16 {%0,%1}, [%2];"
        : "=r"(r[0]), "=r"(r[1]) : "r"(addr));
}
__device__ __forceinline__ void mma_bf16(float* c, const uint32_t* a, const uint32_t* b) {
    asm volatile(
        "mma.sync.aligned.m16n8k16.row.col.f32.bf16.bf16.f32 "
        "{%0,%1,%2,%3}, {%4,%5,%6,%7}, {%8,%9}, {%0,%1,%2,%3};"
        : "+f"(c[0]), "+f"(c[1]), "+f"(c[2]), "+f"(c[3])
        : "r"(a[0]), "r"(a[1]), "r"(a[2]), "r"(a[3]), "r"(b[0]), "r"(b[1]));
}
__device__ __forceinline__ void mma_fp16(float* c, const uint32_t* a, const uint32_t* b) {
    asm volatile(
        "mma.sync.aligned.m16n8k16.row.col.f32.f16.f16.f32 "
        "{%0,%1,%2,%3}, {%4,%5,%6,%7}, {%8,%9}, {%0,%1,%2,%3};"
        : "+f"(c[0]), "+f"(c[1]), "+f"(c[2]), "+f"(c[3])
        : "r"(a[0]), "r"(a[1]), "r"(a[2]), "r"(a[3]), "r"(b[0]), "r"(b[1]));
}
__device__ __forceinline__ uint32_t pack_bf2(__nv_bfloat16 a, __nv_bfloat16 b) {
    __nv_bfloat162 t; t.x = a; t.y = b;
    return *(uint32_t*)&t;
}
__device__ __forceinline__ uint32_t pack_h2(__half a, __half b) {
    __half2 t; t.x = a; t.y = b;
    return *(uint32_t*)&t;
}
__device__ __forceinline__ void split1(float v, __nv_bfloat16& h, __nv_bfloat16& l) {
    h = __float2bfloat16(v);
    l = __float2bfloat16(v - __bfloat162float(h));
}
__device__ __forceinline__ void split1h(float v, __half& h, __half& l) {
    h = __float2half_rn(v);
    l = __float2half_rn(v - __half2float(h));
}

// =====================================================================
// Splitters — device globals bound IN DEVICE CODE only.
// =====================================================================
__global__ __launch_bounds__(256)
void k_split_x(const float* __restrict__ x)
{
    size_t idx = (size_t)blockIdx.x * 256 + threadIdx.x;
    float v = x[idx];
    __nv_bfloat16 h, l; split1(v, h, l);
    g_xh[idx] = h; g_xl[idx] = l;
}

// Q/K/V weight splits in ONE launch: blockIdx.y = sel (0 Q, 1 K, 2 V)
__global__ __launch_bounds__(256)
void k_splitw_qkv(const float* __restrict__ Wq, const float* __restrict__ Wkv)
{
    const int sel = blockIdx.y;
    const float* W = (sel == 0) ? Wq : Wkv;
    const int ldw = (sel == 0) ? INNER : 2 * INNER;
    const int col0 = (sel == 2) ? INNER : 0;

    size_t idx = (size_t)blockIdx.x * 256 + threadIdx.x;   // n*K + k, K=DIM
    int k = (int)(idx % DIM);
    int n = (int)(idx / DIM);
    float v = W[(size_t)k * ldw + col0 + n];
    __nv_bfloat16 h, l; split1(v, h, l);
    __nv_bfloat16* oh = (sel == 0) ? g_wqt_h : (sel == 1) ? g_wkt_h : g_wvt_h;
    __nv_bfloat16* ol = (sel == 0) ? g_wqt_l : (sel == 1) ? g_wkt_l : g_wvt_l;
    oh[idx] = h; ol[idx] = l;
}

__global__ __launch_bounds__(256)
void k_splitw_o(const float* __restrict__ Wo)
{
    size_t idx = (size_t)blockIdx.x * 256 + threadIdx.x;   // n*K + k, K=INNER
    int k = (int)(idx % INNER);
    int n = (int)(idx / INNER);
    float v = Wo[(size_t)k * DIM + n];
    __nv_bfloat16 h, l; split1(v, h, l);
    g_wot_h[idx] = h; g_wot_l[idx] = l;
}

// =====================================================================
// k_vt: V fp32 (g_kv cols [INNER, 2*INNER)) -> fp16 hi/lo transposed [bh][d][j]
// =====================================================================
__global__ __launch_bounds__(256)
void k_vt()
{
    __shared__ __half th[32][33];
    __shared__ __half tl[32][33];
    const int bh = blockIdx.z;
    const int b = bh / NHEAD, h = bh % NHEAD;
    const int j0 = blockIdx.x * 32, d0 = blockIdx.y * 32;
    const int tx = threadIdx.x & 31, ty = threadIdx.x >> 5;   // 32 x 8

    __half* oh = g_vth + (size_t)bh * DHEAD * SEQ;
    __half* ol = g_vtl + (size_t)bh * DHEAD * SEQ;

    #pragma unroll
    for (int i = 0; i < 4; i++) {
        int r = ty + i * 8;   // local j
        float v = g_kv[((size_t)(b * SEQ + j0 + r)) * (2 * INNER) + INNER + h * DHEAD + d0 + tx];
        __half hh, ll; split1h(v, hh, ll);
        th[r][tx] = hh; tl[r][tx] = ll;
    }
    __syncthreads();
    #pragma unroll
    for (int i = 0; i < 4; i++) {
        int r = ty + i * 8;   // local d
        oh[(size_t)(d0 + r) * SEQ + j0 + tx] = th[tx][r];
        ol[(size_t)(d0 + r) * SEQ + j0 + tx] = tl[tx][r];
    }
}

// =====================================================================
// k_gemm_hmma: C = A(MxK) * B^T(NxK), bf16x3, 128x128 tile.
// cp.async double-buffered, KC=16, row stride 24 (conflict-free).
// qkvMode=1: gridDim.z=3; selAB/selC/colOff/ldc derived from blockIdx.z.
// selC: 0 Q-split, 1 K-split, 2 fp32 g_kv, 3 fp32+bias outp.
// =====================================================================
#define GS_STRIDE 24
#define GS_TILE   (128 * GS_STRIDE)

__global__ __launch_bounds__(256)
void k_gemm_hmma(int qkvMode, int selAB, int selC, int K, int colOff, int ldc,
                 float* __restrict__ outp, const float* __restrict__ bias)
{
    __shared__ __nv_bfloat16 sm[2][4][GS_TILE];

    if (qkvMode) {
        int z = blockIdx.z;
        selAB = z; selC = z;
        colOff = (z == 2) ? INNER : 0;
        ldc = (z == 2) ? 2 * INNER : 0;
    }

    const __nv_bfloat16 *Ah, *Al, *Bh, *Bl;
    if (selAB == 3)      { Ah = g_oh; Al = g_ol; Bh = g_wot_h; Bl = g_wot_l; }
    else if (selAB == 2) { Ah = g_xh; Al = g_xl; Bh = g_wvt_h; Bl = g_wvt_l; }
    else if (selAB == 1) { Ah = g_xh; Al = g_xl; Bh = g_wkt_h; Bl = g_wkt_l; }
    else                 { Ah = g_xh; Al = g_xl; Bh = g_wqt_h; Bl = g_wqt_l; }

    const int tid = threadIdx.x;
    const int lane = tid & 31, wid = tid >> 5;
    const int warp_m = wid >> 2, warp_n = wid & 3;
    const int iBase = blockIdx.y * 128, nBase = blockIdx.x * 128;

    float acc[4][4][4];
    #pragma unroll
    for (int m = 0; m < 4; m++)
        #pragma unroll
        for (int n = 0; n < 4; n++)
            #pragma unroll
            for (int k = 0; k < 4; k++) acc[m][n][k] = 0.f;

    const uint32_t uBase = smem_to_u32(sm);

    uint32_t aOff[4], bOff[4];
    #pragma unroll
    for (int mm = 0; mm < 4; mm++)
        aOff[mm] = (uint32_t)(((warp_m * 64 + mm * 16 + (lane & 15)) * GS_STRIDE
                               + (lane >> 4) * 8) * 2);
    #pragma unroll
    for (int nn = 0; nn < 4; nn++)
        bOff[nn] = (uint32_t)(((warp_n * 32 + nn * 8 + (lane & 7)) * GS_STRIDE
                               + ((lane >> 3) & 1) * 8) * 2);

    const __nv_bfloat16* pAh = Ah + (size_t)iBase * K;
    const __nv_bfloat16* pAl = Al + (size_t)iBase * K;
    const __nv_bfloat16* pBh = Bh + (size_t)nBase * K;
    const __nv_bfloat16* pBl = Bl + (size_t)nBase * K;

    const int crow = tid >> 1, chalf = tid & 1;
    const uint32_t cdst = (uint32_t)(crow * GS_STRIDE + chalf * 8) * 2;
    const size_t  csrc = (size_t)crow * K + chalf * 8;

    auto issue = [&](int stage, int k0) {
        uint32_t sb = uBase + (uint32_t)(stage * 4) * (GS_TILE * 2);
        cp16(sb + 0 * (GS_TILE * 2) + cdst, pAh + csrc + k0);
        cp16(sb + 1 * (GS_TILE * 2) + cdst, pAl + csrc + k0);
        cp16(sb + 2 * (GS_TILE * 2) + cdst, pBh + csrc + k0);
        cp16(sb + 3 * (GS_TILE * 2) + cdst, pBl + csrc + k0);
    };

    const int nkt = K / 16;
    issue(0, 0); cp_commit();

    for (int kt = 0; kt < nkt; kt++) {
        const int cur = kt & 1, nxt = cur ^ 1;
        const bool has = (kt + 1) < nkt;

        if (has) { issue(nxt, (kt + 1) * 16); cp_commit(); cp_wait1(); }
        else     { cp_wait0(); }
        __syncthreads();

        const uint32_t sb = uBase + (uint32_t)(cur * 4) * (GS_TILE * 2);
        #pragma unroll
        for (int p = 0; p < 3; p++) {
            uint32_t uA = sb + (uint32_t)(p == 2 ? 1 : 0) * (GS_TILE * 2);
            uint32_t uB = sb + (uint32_t)(p == 1 ? 3 : 2) * (GS_TILE * 2);
            uint32_t a[4][4], b[4][2];
            #pragma unroll
            for (int mm = 0; mm < 4; mm++) ldsm_x4(a[mm], uA + aOff[mm]);
            #pragma unroll
            for (int nn = 0; nn < 4; nn++) ldsm_x2(b[nn], uB + bOff[nn]);
            #pragma unroll
            for (int mm = 0; mm < 4; mm++)
                #pragma unroll
                for (int nn = 0; nn < 4; nn++)
                    mma_bf16(acc[mm][nn], a[mm], b[nn]);
        }
        __syncthreads();
    }

    const int rq = lane >> 2, tg = lane & 3;
    if (selC <= 1) {
        __nv_bfloat16* dh = (selC == 0) ? g_qh : g_kh;
        __nv_bfloat16* dl = (selC == 0) ? g_ql : g_kl;
        #pragma unroll
        for (int mm = 0; mm < 4; mm++) {
            int r0 = iBase + warp_m * 64 + mm * 16 + rq;
            #pragma unroll
            for (int nn = 0; nn < 4; nn++) {
                int c = nBase + warp_n * 32 + nn * 8 + 2 * tg;
                int h = c >> 6, d = c & (DHEAD - 1);
                #pragma unroll
                for (int half = 0; half < 2; half++) {
                    int row = r0 + half * 8;
                    int b = row >> 10, i = row & (SEQ - 1);
                    size_t dst = ((size_t)(b * NHEAD + h) * SEQ + i) * DHEAD + d;
                    float c0 = acc[mm][nn][half * 2 + 0];
                    float c1 = acc[mm][nn][half * 2 + 1];
                    __nv_bfloat16 h0, h1, l0, l1;
                    split1(c0, h0, l0); split1(c1, h1, l1);
                    *(uint32_t*)&dh[dst] = pack_bf2(h0, h1);
                    *(uint32_t*)&dl[dst] = pack_bf2(l0, l1);
                }
            }
        }
    } else {
        float* C = (selC == 2) ? g_kv : outp;
        #pragma unroll
        for (int mm = 0; mm < 4; mm++) {
            int r0 = iBase + warp_m * 64 + mm * 16 + rq;
            #pragma unroll
            for (int nn = 0; nn < 4; nn++) {
                int c = nBase + warp_n * 32 + nn * 8 + 2 * tg;
                float bx = bias ? bias[c] : 0.f;
                float by = bias ? bias[c + 1] : 0.f;
                float2 v0 = { acc[mm][nn][0] + bx, acc[mm][nn][1] + by };
                float2 v1 = { acc[mm][nn][2] + bx, acc[mm][nn][3] + by };
                *(float2*)&C[(size_t)r0 * ldc + colOff + c] = v0;
                *(float2*)&C[(size_t)(r0 + 8) * ldc + colOff + c] = v1;
            }
        }
    }
}

// =====================================================================
// QK^T via mma.sync bf16x3 (validated); streaming stores (.cs) on S
// =====================================================================
__global__ __launch_bounds__(256)
void k_qk_mma()
{
    __shared__ __nv_bfloat16 sA[128 * 72];
    __shared__ __nv_bfloat16 sB[128 * 72];

    const int tid = threadIdx.x;
    const int lane = tid & 31, wid = tid >> 5;
    const int warp_m = wid >> 2, warp_n = wid & 3;
    const int bh = blockIdx.z;
    const int iBase = blockIdx.y * 128, jBase = blockIdx.x * 128;

    const __nv_bfloat16* Qh = g_qh + ((size_t)bh * SEQ + iBase) * DHEAD;
    const __nv_bfloat16* Ql = g_ql + ((size_t)bh * SEQ + iBase) * DHEAD;
    const __nv_bfloat16* Kh = g_kh + ((size_t)bh * SEQ + jBase) * DHEAD;
    const __nv_bfloat16* Kl = g_kl + ((size_t)bh * SEQ + jBase) * DHEAD;

    float acc[4][4][4];
    #pragma unroll
    for (int m = 0; m < 4; m++)
        #pragma unroll
        for (int n = 0; n < 4; n++)
            #pragma unroll
            for (int k = 0; k < 4; k++) acc[m][n][k] = 0.f;

    const uint32_t sA_u = smem_to_u32(sA), sB_u = smem_to_u32(sB);

    uint32_t aOff[4], bOff[4];
    #pragma unroll
    for (int mm = 0; mm < 4; mm++)
        aOff[mm] = (uint32_t)(((warp_m * 64 + mm * 16 + (lane & 15)) * 72
                               + (lane >> 4) * 8) * 2);
    #pragma unroll
    for (int nn = 0; nn < 4; nn++)
        bOff[nn] = (uint32_t)(((warp_n * 32 + nn * 8 + (lane & 7)) * 72
                               + ((lane >> 3) & 1) * 8) * 2);

    auto load_tile = [&](__nv_bfloat16* dst, const __nv_bfloat16* src) {
        #pragma unroll
        for (int it = 0; it < 4; it++) {
            int idx = tid + 256 * it;
            int row = idx >> 3, c8 = (idx & 7) * 8;
            *(float4*)&dst[row * 72 + c8] = *(const float4*)&src[(size_t)row * DHEAD + c8];
        }
    };
    auto pass = [&]() {
        #pragma unroll
        for (int ks = 0; ks < 4; ks++) {
            uint32_t a[4][4], b[4][2];
            #pragma unroll
            for (int mm = 0; mm < 4; mm++) ldsm_x4(a[mm], sA_u + aOff[mm] + ks * 32);
            #pragma unroll
            for (int nn = 0; nn < 4; nn++) ldsm_x2(b[nn], sB_u + bOff[nn] + ks * 32);
            #pragma unroll
            for (int mm = 0; mm < 4; mm++)
                #pragma unroll
                for (int nn = 0; nn < 4; nn++)
                    mma_bf16(acc[mm][nn], a[mm], b[nn]);
        }
    };

    load_tile(sA, Ql); load_tile(sB, Kh);
    __syncthreads();
    pass();
    __syncthreads();
    load_tile(sA, Qh);
    __syncthreads();
    pass();
    __syncthreads();
    load_tile(sB, Kl);
    __syncthreads();
    pass();

    float* S = g_at + (size_t)bh * SEQ * SEQ;
    const int g = lane >> 2, tg = lane & 3;
    #pragma unroll
    for (int mm = 0; mm < 4; mm++) {
        int r0 = iBase + warp_m * 64 + mm * 16 + g;
        #pragma unroll
        for (int nn = 0; nn < 4; nn++) {
            int c = jBase + warp_n * 32 + nn * 8 + 2 * tg;
            float2 v0 = { acc[mm][nn][0] * QK_SCALE, acc[mm][nn][1] * QK_SCALE };
            float2 v1 = { acc[mm][nn][2] * QK_SCALE, acc[mm][nn][3] * QK_SCALE };
            __stcs((float2*)&S[(size_t)r0 * SEQ + c], v0);
            __stcs((float2*)&S[(size_t)(r0 + 8) * SEQ + c], v1);
        }
    }
}

// =====================================================================
// Fused talking-heads (R13 version: no max pass, incremental premix)
// =====================================================================
__global__ __launch_bounds__(512)
void k_mix_softmax(const float* __restrict__ pre, const float* __restrict__ post)
{
    __shared__ float sp[NHEAD * NHEAD];
    __shared__ float sq[NHEAD * NHEAD];
    __shared__ float red[NHEAD][16];
    __shared__ float bc[NHEAD];

    const int tid = threadIdx.x;
    const int lane = tid & 31, wid = tid >> 5;

    if (tid < NHEAD * NHEAD) { sp[tid] = pre[tid]; sq[tid] = post[tid]; }
    __syncthreads();

    const int b = blockIdx.x >> 10;
    const int i = blockIdx.x & (SEQ - 1);
    float* base = g_at + (size_t)b * NHEAD * SEQ * SEQ + (size_t)i * SEQ + tid * 2;

    float2 t2[NHEAD];
    #pragma unroll
    for (int g = 0; g < NHEAD; g++) { t2[g].x = 0.f; t2[g].y = 0.f; }
    #pragma unroll
    for (int h = 0; h < NHEAD; h++) {
        float2 s = __ldcs((const float2*)&base[(size_t)h * SEQ * SEQ]);
        #pragma unroll
        for (int g = 0; g < NHEAD; g++) {
            float w = sp[h * NHEAD + g];
            t2[g].x = fmaf(s.x, w, t2[g].x);
            t2[g].y = fmaf(s.y, w, t2[g].y);
        }
    }

    #pragma unroll
    for (int g = 0; g < NHEAD; g++) {
        t2[g].x = __expf(t2[g].x);
        t2[g].y = __expf(t2[g].y);
    }

    #pragma unroll
    for (int g = 0; g < NHEAD; g++) {
        float v = t2[g].x + t2[g].y;
        #pragma unroll
        for (int o = 16; o; o >>= 1) v += __shfl_xor_sync(0xffffffffu, v, o);
        if (lane == 0) red[g][wid] = v;
    }
    __syncthreads();
    if (tid < NHEAD) {
        float v = red[tid][0];
        #pragma unroll
        for (int k = 1; k < 16; k++) v += red[tid][k];
        bc[tid] = 1.f / v;
    }
    __syncthreads();

    #pragma unroll
    for (int g = 0; g < NHEAD; g++) { t2[g].x *= bc[g]; t2[g].y *= bc[g]; }

    #pragma unroll
    for (int g2 = 0; g2 < NHEAD; g2++) {
        float ux = 0.f, uy = 0.f;
        #pragma unroll
        for (int g = 0; g < NHEAD; g++) {
            float w = sq[g * NHEAD + g2];
            ux = fmaf(t2[g].x, w, ux);
            uy = fmaf(t2[g].y, w, uy);
        }
        float2 u = {ux, uy};
        __stcs((float2*)&base[(size_t)g2 * SEQ * SEQ], u);
    }
}

// =====================================================================
// k_av_mma: O = P @ V per (b,h), fp16 2-pass (P fp16, V fp16 hi/lo).
// A-fragments (P) shared across both passes. Register-staged prefetch.
// Epilogue writes O bf16 hi/lo directly (g_oh/g_ol).
// =====================================================================
__global__ __launch_bounds__(256)
void k_av_mma()
{
    __shared__ __half sP [128 * 40];
    __shared__ __half sVh[64 * 40];
    __shared__ __half sVl[64 * 40];

    const int tid = threadIdx.x;
    const int lane = tid & 31, wid = tid >> 5;
    const int warp_m = wid >> 1, warp_n = wid & 1;   // 4m x 2n
    const int bh = blockIdx.y;
    const int b = bh / NHEAD, h = bh % NHEAD;
    const int iBase = blockIdx.x * 128;

    const float* P = g_at + (size_t)bh * SEQ * SEQ + (size_t)iBase * SEQ;
    const __half* Vh = g_vth + (size_t)bh * DHEAD * SEQ;
    const __half* Vl = g_vtl + (size_t)bh * DHEAD * SEQ;

    float acc[2][4][4];
    #pragma unroll
    for (int m = 0; m < 2; m++)
        #pragma unroll
        for (int n = 0; n < 4; n++)
            #pragma unroll
            for (int k = 0; k < 4; k++) acc[m][n][k] = 0.f;

    const uint32_t uP = smem_to_u32(sP);
    const uint32_t uVh = smem_to_u32(sVh), uVl = smem_to_u32(sVl);

    uint32_t aOff[2], bOff[4];
    #pragma unroll
    for (int mm = 0; mm < 2; mm++)
        aOff[mm] = (uint32_t)(((warp_m * 32 + mm * 16 + (lane & 15)) * 40
                               + (lane >> 4) * 8) * 2);
    #pragma unroll
    for (int nn = 0; nn < 4; nn++)
        bOff[nn] = (uint32_t)(((warp_n * 32 + nn * 8 + (lane & 7)) * 40
                               + ((lane >> 3) & 1) * 8) * 2);

    const int prow = tid >> 3, pc4 = (tid & 7) * 4;
    const int vrow = tid >> 2, vc8 = (tid & 3) * 8;

    #pragma unroll
    for (int it = 0; it < 4; it++) {
        int row = prow + 32 * it;
        float4 v = __ldcs((const float4*)&P[(size_t)row * SEQ + pc4]);
        *(uint2*)&sP[row * 40 + pc4] = make_uint2(
            pack_h2(__float2half_rn(v.x), __float2half_rn(v.y)),
            pack_h2(__float2half_rn(v.z), __float2half_rn(v.w)));
    }
    *(float4*)&sVh[vrow * 40 + vc8] = *(const float4*)&Vh[(size_t)vrow * SEQ + vc8];
    *(float4*)&sVl[vrow * 40 + vc8] = *(const float4*)&Vl[(size_t)vrow * SEQ + vc8];
    __syncthreads();

    float4 rP[4], rVh, rVl;
    const int nkt = SEQ / 32;   // 32

    for (int kt = 0; kt < nkt; kt++) {
        const bool has = (kt + 1) < nkt;
        const int k0n = (kt + 1) * 32;

        if (has) {
            #pragma unroll
            for (int it = 0; it < 4; it++) {
                int row = prow + 32 * it;
                rP[it] = __ldcs((const float4*)&P[(size_t)row * SEQ + k0n + pc4]);
            }
            rVh = *(const float4*)&Vh[(size_t)vrow * SEQ + k0n + vc8];
            rVl = *(const float4*)&Vl[(size_t)vrow * SEQ + k0n + vc8];
        }

        #pragma unroll
        for (int ks = 0; ks < 2; ks++) {
            uint32_t a[2][4], bh2[4][2], bl2[4][2];
            #pragma unroll
            for (int mm = 0; mm < 2; mm++) ldsm_x4(a[mm], uP + aOff[mm] + ks * 32);
            #pragma unroll
            for (int nn = 0; nn < 4; nn++) ldsm_x2(bh2[nn], uVh + bOff[nn] + ks * 32);
            #pragma unroll
            for (int nn = 0; nn < 4; nn++) ldsm_x2(bl2[nn], uVl + bOff[nn] + ks * 32);
            #pragma unroll
            for (int mm = 0; mm < 2; mm++)
                #pragma unroll
                for (int nn = 0; nn < 4; nn++) {
                    mma_fp16(acc[mm][nn], a[mm], bh2[nn]);
                    mma_fp16(acc[mm][nn], a[mm], bl2[nn]);
                }
        }

        if (has) {
            __syncthreads();
            #pragma unroll
            for (int it = 0; it < 4; it++) {
                int row = prow + 32 * it;
                *(uint2*)&sP[row * 40 + pc4] = make_uint2(
                    pack_h2(__float2half_rn(rP[it].x), __float2half_rn(rP[it].y)),
                    pack_h2(__float2half_rn(rP[it].z), __float2half_rn(rP[it].w)));
            }
            *(float4*)&sVh[vrow * 40 + vc8] = rVh;
            *(float4*)&sVl[vrow * 40 + vc8] = rVl;
            __syncthreads();
        }
    }

    const int rq = lane >> 2, tg = lane & 3;
    #pragma unroll
    for (int mm = 0; mm < 2; mm++) {
        int rloc = warp_m * 32 + mm * 16 + rq;
        #pragma unroll
        for (int nn = 0; nn < 4; nn++) {
            int c = h * DHEAD + warp_n * 32 + nn * 8 + 2 * tg;
            #pragma unroll
            for (int half = 0; half < 2; half++) {
                size_t row = (size_t)b * SEQ + iBase + rloc + half * 8;
                size_t dst = row * INNER + c;
                float c0 = acc[mm][nn][half * 2 + 0];
                float c1 = acc[mm][nn][half * 2 + 1];
                __nv_bfloat16 h0, h1, l0, l1;
                split1(c0, h0, l0); split1(c1, h1, l1);
                *(uint32_t*)&g_oh[dst] = pack_bf2(h0, h1);
                *(uint32_t*)&g_ol[dst] = pack_bf2(l0, l1);
            }
        }
    }
}

// =====================================================================
// launch — kernel launches ONLY; NO device-global symbols referenced here.
// 4th launch (index 3) = merged QKV gemm, lands in the ncu capture window.
// =====================================================================
extern "C" void kernel_launch(void* const* d_in, const int* in_sizes, int n_in,
                              void* d_out, int out_size)
{
    const float* x    = (const float*)d_in[0];
    const float* Wq   = (const float*)d_in[1];
    const float* Wkv  = (const float*)d_in[2];
    const float* pre  = (const float*)d_in[3];
    const float* post = (const float*)d_in[4];
    const float* Wo   = (const float*)d_in[5];
    const float* bo   = (const float*)d_in[6];
    float* out = (float*)d_out;

    k_split_x<<<(int)(X_ELEMS / 256), 256>>>(x);                              // 0
    k_splitw_qkv<<<dim3(DIM * INNER / 256, 3), 256>>>(Wq, Wkv);               // 1
    k_splitw_o<<<INNER * DIM / 256, 256>>>(Wo);                               // 2

    // merged Q/K/V projections (grid.z = 3), index 3
    k_gemm_hmma<<<dim3(INNER / 128, MTOT / 128, 3), 256>>>(
        1, 0, 0, DIM, 0, 0, nullptr, nullptr);

    // attention
    k_vt<<<dim3(SEQ / 32, DHEAD / 32, BATCH * NHEAD), 256>>>();
    k_qk_mma<<<dim3(SEQ / 128, SEQ / 128, BATCH * NHEAD), 256>>>();
    k_mix_softmax<<<BATCH * SEQ, 512>>>(pre, post);
    k_av_mma<<<dim3(SEQ / 128, BATCH * NHEAD), 256>>>();   // -> g_oh/g_ol

    // output projection (fp32 + bias to harness out)
    k_gemm_hmma<<<dim3(DIM / 128, MTOT / 128), 256>>>(
        0, 3, 3, INNER, 0, DIM, out, bo);
}

// round 15
// speedup vs baseline: 1.0462x; 1.0462x over previous
#include <cuda_runtime.h>
#include <cuda_bf16.h>
#include <cuda_fp16.h>
#include <cstddef>
#include <cstdint>

#define BATCH 16
#define SEQ   1024
#define DIM   768
#define NHEAD 12
#define DHEAD 64
#define INNER 768            // NHEAD*DHEAD
#define QK_SCALE 0.125f      // DHEAD^-0.5
#define MTOT (BATCH * SEQ)   // 16384

// ---------------- scratch (device globals; no allocation allowed) ----------------
__device__ float g_kv[(size_t)MTOT * 2 * INNER];                    // 101 MB (V half used)
__device__ float g_at[(size_t)BATCH * NHEAD * SEQ * SEQ];           // 805 MB
#define QK_ELEMS ((size_t)BATCH * NHEAD * SEQ * DHEAD)              // 12.58M
#define X_ELEMS  ((size_t)MTOT * INNER)                             // 12.58M
// bf16 splits
__device__ __nv_bfloat16 g_xh[X_ELEMS], g_xl[X_ELEMS];
__device__ __nv_bfloat16 g_oh[X_ELEMS], g_ol[X_ELEMS];
__device__ __nv_bfloat16 g_qh[QK_ELEMS], g_ql[QK_ELEMS];
__device__ __nv_bfloat16 g_kh[QK_ELEMS], g_kl[QK_ELEMS];
// V transposed+split [b,h,d,j]  (fp16 for the 2-pass AV)
__device__ __half g_vth[QK_ELEMS], g_vtl[QK_ELEMS];
// transposed+split weights [N][K]
__device__ __nv_bfloat16 g_wqt_h[DIM * INNER], g_wqt_l[DIM * INNER];
__device__ __nv_bfloat16 g_wkt_h[DIM * INNER], g_wkt_l[DIM * INNER];
__device__ __nv_bfloat16 g_wvt_h[DIM * INNER], g_wvt_l[DIM * INNER];
__device__ __nv_bfloat16 g_wot_h[INNER * DIM], g_wot_l[INNER * DIM];

// ---------------- cp.async helpers ----------------
__device__ __forceinline__ void cp16(uint32_t saddr, const void* gptr) {
    asm volatile("cp.async.cg.shared.global [%0], [%1], 16;" :: "r"(saddr), "l"(gptr));
}
__device__ __forceinline__ void cp_commit() { asm volatile("cp.async.commit_group;"); }
__device__ __forceinline__ void cp_wait0()  { asm volatile("cp.async.wait_group 0;"); }
__device__ __forceinline__ void cp_wait1()  { asm volatile("cp.async.wait_group 1;"); }

// ---------------- mma.sync / ldmatrix helpers (baseline PTX) ----------------
__device__ __forceinline__ uint32_t smem_to_u32(const void* p) {
    uint32_t a;
    asm("{ .reg .u64 t; cvta.to.shared.u64 t, %1; cvt.u32.u64 %0, t; }" : "=r"(a) : "l"(p));
    return a;
}
__device__ __forceinline__ void ldsm_x4(uint32_t* r, uint32_t addr) {
    asm volatile("ldmatrix.sync.aligned.m8n8.x4.shared.b16 {%0,%1,%2,%3}, [%4];"
        : "=r"(r[0]), "=r"(r[1]), "=r"(r[2]), "=r"(r[3]) : "r"(addr));
}
__device__ __forceinline__ void ldsm_x2(uint32_t* r, uint32_t addr) {
    asm volatile("ldmatrix.sync.aligned.m8n8.x2.shared.b16 {%0,%1}, [%2];"
        : "=r"(r[0]), "=r"(r[1]) : "r"(addr));
}
__device__ __forceinline__ void mma_bf16(float* c, const uint32_t* a, const uint32_t* b) {
    asm volatile(
        "mma.sync.aligned.m16n8k16.row.col.f32.bf16.bf16.f32 "
        "{%0,%1,%2,%3}, {%4,%5,%6,%7}, {%8,%9}, {%0,%1,%2,%3};"
        : "+f"(c[0]), "+f"(c[1]), "+f"(c[2]), "+f"(c[3])
        : "r"(a[0]), "r"(a[1]), "r"(a[2]), "r"(a[3]), "r"(b[0]), "r"(b[1]));
}
__device__ __forceinline__ void mma_fp16(float* c, const uint32_t* a, const uint32_t* b) {
    asm volatile(
        "mma.sync.aligned.m16n8k16.row.col.f32.f16.f16.f32 "
        "{%0,%1,%2,%3}, {%4,%5,%6,%7}, {%8,%9}, {%0,%1,%2,%3};"
        : "+f"(c[0]), "+f"(c[1]), "+f"(c[2]), "+f"(c[3])
        : "r"(a[0]), "r"(a[1]), "r"(a[2]), "r"(a[3]), "r"(b[0]), "r"(b[1]));
}
__device__ __forceinline__ uint32_t pack_bf2(__nv_bfloat16 a, __nv_bfloat16 b) {
    __nv_bfloat162 t; t.x = a; t.y = b;
    return *(uint32_t*)&t;
}
__device__ __forceinline__ uint32_t pack_h2(__half a, __half b) {
    __half2 t; t.x = a; t.y = b;
    return *(uint32_t*)&t;
}
__device__ __forceinline__ void split1(float v, __nv_bfloat16& h, __nv_bfloat16& l) {
    h = __float2bfloat16(v);
    l = __float2bfloat16(v - __bfloat162float(h));
}
__device__ __forceinline__ void split1h(float v, __half& h, __half& l) {
    h = __float2half_rn(v);
    l = __float2half_rn(v - __half2float(h));
}

// =====================================================================
// Splitters
// =====================================================================
__global__ __launch_bounds__(256)
void k_split_x(const float* __restrict__ x)
{
    size_t idx = (size_t)blockIdx.x * 256 + threadIdx.x;
    float v = x[idx];
    __nv_bfloat16 h, l; split1(v, h, l);
    g_xh[idx] = h; g_xl[idx] = l;
}

// Q/K/V weight splits in ONE launch: blockIdx.y = sel (0 Q, 1 K, 2 V)
__global__ __launch_bounds__(256)
void k_splitw_qkv(const float* __restrict__ Wq, const float* __restrict__ Wkv)
{
    const int sel = blockIdx.y;
    const float* W = (sel == 0) ? Wq : Wkv;
    const int ldw = (sel == 0) ? INNER : 2 * INNER;
    const int col0 = (sel == 2) ? INNER : 0;

    size_t idx = (size_t)blockIdx.x * 256 + threadIdx.x;   // n*K + k, K=DIM
    int k = (int)(idx % DIM);
    int n = (int)(idx / DIM);
    float v = W[(size_t)k * ldw + col0 + n];
    __nv_bfloat16 h, l; split1(v, h, l);
    __nv_bfloat16* oh = (sel == 0) ? g_wqt_h : (sel == 1) ? g_wkt_h : g_wvt_h;
    __nv_bfloat16* ol = (sel == 0) ? g_wqt_l : (sel == 1) ? g_wkt_l : g_wvt_l;
    oh[idx] = h; ol[idx] = l;
}

__global__ __launch_bounds__(256)
void k_splitw_o(const float* __restrict__ Wo)
{
    size_t idx = (size_t)blockIdx.x * 256 + threadIdx.x;   // n*K + k, K=INNER
    int k = (int)(idx % INNER);
    int n = (int)(idx / INNER);
    float v = Wo[(size_t)k * DIM + n];
    __nv_bfloat16 h, l; split1(v, h, l);
    g_wot_h[idx] = h; g_wot_l[idx] = l;
}

// =====================================================================
// k_vt: V fp32 (g_kv cols [INNER, 2*INNER)) -> fp16 hi/lo transposed [bh][d][j]
// =====================================================================
__global__ __launch_bounds__(256)
void k_vt()
{
    __shared__ __half th[32][33];
    __shared__ __half tl[32][33];
    const int bh = blockIdx.z;
    const int b = bh / NHEAD, h = bh % NHEAD;
    const int j0 = blockIdx.x * 32, d0 = blockIdx.y * 32;
    const int tx = threadIdx.x & 31, ty = threadIdx.x >> 5;   // 32 x 8

    __half* oh = g_vth + (size_t)bh * DHEAD * SEQ;
    __half* ol = g_vtl + (size_t)bh * DHEAD * SEQ;

    #pragma unroll
    for (int i = 0; i < 4; i++) {
        int r = ty + i * 8;   // local j
        float v = g_kv[((size_t)(b * SEQ + j0 + r)) * (2 * INNER) + INNER + h * DHEAD + d0 + tx];
        __half hh, ll; split1h(v, hh, ll);
        th[r][tx] = hh; tl[r][tx] = ll;
    }
    __syncthreads();
    #pragma unroll
    for (int i = 0; i < 4; i++) {
        int r = ty + i * 8;   // local d
        oh[(size_t)(d0 + r) * SEQ + j0 + tx] = th[tx][r];
        ol[(size_t)(d0 + r) * SEQ + j0 + tx] = tl[tx][r];
    }
}

// =====================================================================
// k_gemm_hmma<SELAB, SELC>: compile-time specialized HMMA GEMM.
// C = A(MxK) * B^T(NxK), bf16x3, 128x128 tile, cp.async double-buffered,
// KC=16, row stride 24 (conflict-free). Static smem 49152 B.
// SELAB: 0 X*Wq, 1 X*Wk, 2 X*Wv, 3 O*Wo.
// SELC:  0 Q-split head-major, 1 K-split head-major, 2 fp32 g_kv, 3 fp32+bias outp.
// =====================================================================
#define GS_STRIDE 24
#define GS_TILE   (128 * GS_STRIDE)

template<int SELAB, int SELC, int K, int COLOFF, int LDC>
__global__ __launch_bounds__(256)
void k_gemm_hmma(float* __restrict__ outp, const float* __restrict__ bias)
{
    __shared__ __nv_bfloat16 sm[2][4][GS_TILE];

    const __nv_bfloat16* Ah = (SELAB == 3) ? g_oh : g_xh;
    const __nv_bfloat16* Al = (SELAB == 3) ? g_ol : g_xl;
    const __nv_bfloat16* Bh = (SELAB == 0) ? g_wqt_h : (SELAB == 1) ? g_wkt_h
                            : (SELAB == 2) ? g_wvt_h : g_wot_h;
    const __nv_bfloat16* Bl = (SELAB == 0) ? g_wqt_l : (SELAB == 1) ? g_wkt_l
                            : (SELAB == 2) ? g_wvt_l : g_wot_l;

    const int tid = threadIdx.x;
    const int lane = tid & 31, wid = tid >> 5;
    const int warp_m = wid >> 2, warp_n = wid & 3;
    const int iBase = blockIdx.y * 128, nBase = blockIdx.x * 128;

    float acc[4][4][4];
    #pragma unroll
    for (int m = 0; m < 4; m++)
        #pragma unroll
        for (int n = 0; n < 4; n++)
            #pragma unroll
            for (int k = 0; k < 4; k++) acc[m][n][k] = 0.f;

    const uint32_t uBase = smem_to_u32(sm);

    uint32_t aOff[4], bOff[4];
    #pragma unroll
    for (int mm = 0; mm < 4; mm++)
        aOff[mm] = (uint32_t)(((warp_m * 64 + mm * 16 + (lane & 15)) * GS_STRIDE
                               + (lane >> 4) * 8) * 2);
    #pragma unroll
    for (int nn = 0; nn < 4; nn++)
        bOff[nn] = (uint32_t)(((warp_n * 32 + nn * 8 + (lane & 7)) * GS_STRIDE
                               + ((lane >> 3) & 1) * 8) * 2);

    const __nv_bfloat16* pAh = Ah + (size_t)iBase * K;
    const __nv_bfloat16* pAl = Al + (size_t)iBase * K;
    const __nv_bfloat16* pBh = Bh + (size_t)nBase * K;
    const __nv_bfloat16* pBl = Bl + (size_t)nBase * K;

    const int crow = tid >> 1, chalf = tid & 1;
    const uint32_t cdst = (uint32_t)(crow * GS_STRIDE + chalf * 8) * 2;
    const size_t  csrc = (size_t)crow * K + chalf * 8;

    auto issue = [&](int stage, int k0) {
        uint32_t sb = uBase + (uint32_t)(stage * 4) * (GS_TILE * 2);
        cp16(sb + 0 * (GS_TILE * 2) + cdst, pAh + csrc + k0);
        cp16(sb + 1 * (GS_TILE * 2) + cdst, pAl + csrc + k0);
        cp16(sb + 2 * (GS_TILE * 2) + cdst, pBh + csrc + k0);
        cp16(sb + 3 * (GS_TILE * 2) + cdst, pBl + csrc + k0);
    };

    const int nkt = K / 16;
    issue(0, 0); cp_commit();

    for (int kt = 0; kt < nkt; kt++) {
        const int cur = kt & 1, nxt = cur ^ 1;
        const bool has = (kt + 1) < nkt;

        if (has) { issue(nxt, (kt + 1) * 16); cp_commit(); cp_wait1(); }
        else     { cp_wait0(); }
        __syncthreads();

        const uint32_t sb = uBase + (uint32_t)(cur * 4) * (GS_TILE * 2);
        #pragma unroll
        for (int p = 0; p < 3; p++) {
            uint32_t uA = sb + (uint32_t)(p == 2 ? 1 : 0) * (GS_TILE * 2);
            uint32_t uB = sb + (uint32_t)(p == 1 ? 3 : 2) * (GS_TILE * 2);
            uint32_t a[4][4], b[4][2];
            #pragma unroll
            for (int mm = 0; mm < 4; mm++) ldsm_x4(a[mm], uA + aOff[mm]);
            #pragma unroll
            for (int nn = 0; nn < 4; nn++) ldsm_x2(b[nn], uB + bOff[nn]);
            #pragma unroll
            for (int mm = 0; mm < 4; mm++)
                #pragma unroll
                for (int nn = 0; nn < 4; nn++)
                    mma_bf16(acc[mm][nn], a[mm], b[nn]);
        }
        __syncthreads();
    }

    const int rq = lane >> 2, tg = lane & 3;
    if (SELC <= 1) {
        __nv_bfloat16* dh = (SELC == 0) ? g_qh : g_kh;
        __nv_bfloat16* dl = (SELC == 0) ? g_ql : g_kl;
        #pragma unroll
        for (int mm = 0; mm < 4; mm++) {
            int r0 = iBase + warp_m * 64 + mm * 16 + rq;
            #pragma unroll
            for (int nn = 0; nn < 4; nn++) {
                int c = nBase + warp_n * 32 + nn * 8 + 2 * tg;
                int h = c >> 6, d = c & (DHEAD - 1);
                #pragma unroll
                for (int half = 0; half < 2; half++) {
                    int row = r0 + half * 8;
                    int b = row >> 10, i = row & (SEQ - 1);
                    size_t dst = ((size_t)(b * NHEAD + h) * SEQ + i) * DHEAD + d;
                    float c0 = acc[mm][nn][half * 2 + 0];
                    float c1 = acc[mm][nn][half * 2 + 1];
                    __nv_bfloat16 h0, h1, l0, l1;
                    split1(c0, h0, l0); split1(c1, h1, l1);
                    *(uint32_t*)&dh[dst] = pack_bf2(h0, h1);
                    *(uint32_t*)&dl[dst] = pack_bf2(l0, l1);
                }
            }
        }
    } else {
        float* C = (SELC == 2) ? g_kv : outp;
        #pragma unroll
        for (int mm = 0; mm < 4; mm++) {
            int r0 = iBase + warp_m * 64 + mm * 16 + rq;
            #pragma unroll
            for (int nn = 0; nn < 4; nn++) {
                int c = nBase + warp_n * 32 + nn * 8 + 2 * tg;
                float bx = (SELC == 3) ? bias[c] : 0.f;
                float by = (SELC == 3) ? bias[c + 1] : 0.f;
                float2 v0 = { acc[mm][nn][0] + bx, acc[mm][nn][1] + by };
                float2 v1 = { acc[mm][nn][2] + bx, acc[mm][nn][3] + by };
                *(float2*)&C[(size_t)r0 * LDC + COLOFF + c] = v0;
                *(float2*)&C[(size_t)(r0 + 8) * LDC + COLOFF + c] = v1;
            }
        }
    }
}

// =====================================================================
// QK^T via mma.sync bf16x3 (validated); streaming stores (.cs) on S
// =====================================================================
__global__ __launch_bounds__(256)
void k_qk_mma()
{
    __shared__ __nv_bfloat16 sA[128 * 72];
    __shared__ __nv_bfloat16 sB[128 * 72];

    const int tid = threadIdx.x;
    const int lane = tid & 31, wid = tid >> 5;
    const int warp_m = wid >> 2, warp_n = wid & 3;
    const int bh = blockIdx.z;
    const int iBase = blockIdx.y * 128, jBase = blockIdx.x * 128;

    const __nv_bfloat16* Qh = g_qh + ((size_t)bh * SEQ + iBase) * DHEAD;
    const __nv_bfloat16* Ql = g_ql + ((size_t)bh * SEQ + iBase) * DHEAD;
    const __nv_bfloat16* Kh = g_kh + ((size_t)bh * SEQ + jBase) * DHEAD;
    const __nv_bfloat16* Kl = g_kl + ((size_t)bh * SEQ + jBase) * DHEAD;

    float acc[4][4][4];
    #pragma unroll
    for (int m = 0; m < 4; m++)
        #pragma unroll
        for (int n = 0; n < 4; n++)
            #pragma unroll
            for (int k = 0; k < 4; k++) acc[m][n][k] = 0.f;

    const uint32_t sA_u = smem_to_u32(sA), sB_u = smem_to_u32(sB);

    uint32_t aOff[4], bOff[4];
    #pragma unroll
    for (int mm = 0; mm < 4; mm++)
        aOff[mm] = (uint32_t)(((warp_m * 64 + mm * 16 + (lane & 15)) * 72
                               + (lane >> 4) * 8) * 2);
    #pragma unroll
    for (int nn = 0; nn < 4; nn++)
        bOff[nn] = (uint32_t)(((warp_n * 32 + nn * 8 + (lane & 7)) * 72
                               + ((lane >> 3) & 1) * 8) * 2);

    auto load_tile = [&](__nv_bfloat16* dst, const __nv_bfloat16* src) {
        #pragma unroll
        for (int it = 0; it < 4; it++) {
            int idx = tid + 256 * it;
            int row = idx >> 3, c8 = (idx & 7) * 8;
            *(float4*)&dst[row * 72 + c8] = *(const float4*)&src[(size_t)row * DHEAD + c8];
        }
    };
    auto pass = [&]() {
        #pragma unroll
        for (int ks = 0; ks < 4; ks++) {
            uint32_t a[4][4], b[4][2];
            #pragma unroll
            for (int mm = 0; mm < 4; mm++) ldsm_x4(a[mm], sA_u + aOff[mm] + ks * 32);
            #pragma unroll
            for (int nn = 0; nn < 4; nn++) ldsm_x2(b[nn], sB_u + bOff[nn] + ks * 32);
            #pragma unroll
            for (int mm = 0; mm < 4; mm++)
                #pragma unroll
                for (int nn = 0; nn < 4; nn++)
                    mma_bf16(acc[mm][nn], a[mm], b[nn]);
        }
    };

    load_tile(sA, Ql); load_tile(sB, Kh);
    __syncthreads();
    pass();
    __syncthreads();
    load_tile(sA, Qh);
    __syncthreads();
    pass();
    __syncthreads();
    load_tile(sB, Kl);
    __syncthreads();
    pass();

    float* S = g_at + (size_t)bh * SEQ * SEQ;
    const int g = lane >> 2, tg = lane & 3;
    #pragma unroll
    for (int mm = 0; mm < 4; mm++) {
        int r0 = iBase + warp_m * 64 + mm * 16 + g;
        #pragma unroll
        for (int nn = 0; nn < 4; nn++) {
            int c = jBase + warp_n * 32 + nn * 8 + 2 * tg;
            float2 v0 = { acc[mm][nn][0] * QK_SCALE, acc[mm][nn][1] * QK_SCALE };
            float2 v1 = { acc[mm][nn][2] * QK_SCALE, acc[mm][nn][3] * QK_SCALE };
            __stcs((float2*)&S[(size_t)r0 * SEQ + c], v0);
            __stcs((float2*)&S[(size_t)(r0 + 8) * SEQ + c], v1);
        }
    }
}

// =====================================================================
// Fused talking-heads (no max pass, incremental premix)
// =====================================================================
__global__ __launch_bounds__(512)
void k_mix_softmax(const float* __restrict__ pre, const float* __restrict__ post)
{
    __shared__ float sp[NHEAD * NHEAD];
    __shared__ float sq[NHEAD * NHEAD];
    __shared__ float red[NHEAD][16];
    __shared__ float bc[NHEAD];

    const int tid = threadIdx.x;
    const int lane = tid & 31, wid = tid >> 5;

    if (tid < NHEAD * NHEAD) { sp[tid] = pre[tid]; sq[tid] = post[tid]; }
    __syncthreads();

    const int b = blockIdx.x >> 10;
    const int i = blockIdx.x & (SEQ - 1);
    float* base = g_at + (size_t)b * NHEAD * SEQ * SEQ + (size_t)i * SEQ + tid * 2;

    float2 t2[NHEAD];
    #pragma unroll
    for (int g = 0; g < NHEAD; g++) { t2[g].x = 0.f; t2[g].y = 0.f; }
    #pragma unroll
    for (int h = 0; h < NHEAD; h++) {
        float2 s = __ldcs((const float2*)&base[(size_t)h * SEQ * SEQ]);
        #pragma unroll
        for (int g = 0; g < NHEAD; g++) {
            float w = sp[h * NHEAD + g];
            t2[g].x = fmaf(s.x, w, t2[g].x);
            t2[g].y = fmaf(s.y, w, t2[g].y);
        }
    }

    #pragma unroll
    for (int g = 0; g < NHEAD; g++) {
        t2[g].x = __expf(t2[g].x);
        t2[g].y = __expf(t2[g].y);
    }

    #pragma unroll
    for (int g = 0; g < NHEAD; g++) {
        float v = t2[g].x + t2[g].y;
        #pragma unroll
        for (int o = 16; o; o >>= 1) v += __shfl_xor_sync(0xffffffffu, v, o);
        if (lane == 0) red[g][wid] = v;
    }
    __syncthreads();
    if (tid < NHEAD) {
        float v = red[tid][0];
        #pragma unroll
        for (int k = 1; k < 16; k++) v += red[tid][k];
        bc[tid] = 1.f / v;
    }
    __syncthreads();

    #pragma unroll
    for (int g = 0; g < NHEAD; g++) { t2[g].x *= bc[g]; t2[g].y *= bc[g]; }

    #pragma unroll
    for (int g2 = 0; g2 < NHEAD; g2++) {
        float ux = 0.f, uy = 0.f;
        #pragma unroll
        for (int g = 0; g < NHEAD; g++) {
            float w = sq[g * NHEAD + g2];
            ux = fmaf(t2[g].x, w, ux);
            uy = fmaf(t2[g].y, w, uy);
        }
        float2 u = {ux, uy};
        __stcs((float2*)&base[(size_t)g2 * SEQ * SEQ], u);
    }
}

// =====================================================================
// k_av_mma: O = P @ V per (b,h), fp16 2-pass (P fp16, V fp16 hi/lo).
// =====================================================================
__global__ __launch_bounds__(256)
void k_av_mma()
{
    __shared__ __half sP [128 * 40];
    __shared__ __half sVh[64 * 40];
    __shared__ __half sVl[64 * 40];

    const int tid = threadIdx.x;
    const int lane = tid & 31, wid = tid >> 5;
    const int warp_m = wid >> 1, warp_n = wid & 1;   // 4m x 2n
    const int bh = blockIdx.y;
    const int b = bh / NHEAD, h = bh % NHEAD;
    const int iBase = blockIdx.x * 128;

    const float* P = g_at + (size_t)bh * SEQ * SEQ + (size_t)iBase * SEQ;
    const __half* Vh = g_vth + (size_t)bh * DHEAD * SEQ;
    const __half* Vl = g_vtl + (size_t)bh * DHEAD * SEQ;

    float acc[2][4][4];
    #pragma unroll
    for (int m = 0; m < 2; m++)
        #pragma unroll
        for (int n = 0; n < 4; n++)
            #pragma unroll
            for (int k = 0; k < 4; k++) acc[m][n][k] = 0.f;

    const uint32_t uP = smem_to_u32(sP);
    const uint32_t uVh = smem_to_u32(sVh), uVl = smem_to_u32(sVl);

    uint32_t aOff[2], bOff[4];
    #pragma unroll
    for (int mm = 0; mm < 2; mm++)
        aOff[mm] = (uint32_t)(((warp_m * 32 + mm * 16 + (lane & 15)) * 40
                               + (lane >> 4) * 8) * 2);
    #pragma unroll
    for (int nn = 0; nn < 4; nn++)
        bOff[nn] = (uint32_t)(((warp_n * 32 + nn * 8 + (lane & 7)) * 40
                               + ((lane >> 3) & 1) * 8) * 2);

    const int prow = tid >> 3, pc4 = (tid & 7) * 4;
    const int vrow = tid >> 2, vc8 = (tid & 3) * 8;

    #pragma unroll
    for (int it = 0; it < 4; it++) {
        int row = prow + 32 * it;
        float4 v = __ldcs((const float4*)&P[(size_t)row * SEQ + pc4]);
        *(uint2*)&sP[row * 40 + pc4] = make_uint2(
            pack_h2(__float2half_rn(v.x), __float2half_rn(v.y)),
            pack_h2(__float2half_rn(v.z), __float2half_rn(v.w)));
    }
    *(float4*)&sVh[vrow * 40 + vc8] = *(const float4*)&Vh[(size_t)vrow * SEQ + vc8];
    *(float4*)&sVl[vrow * 40 + vc8] = *(const float4*)&Vl[(size_t)vrow * SEQ + vc8];
    __syncthreads();

    float4 rP[4], rVh, rVl;
    const int nkt = SEQ / 32;   // 32

    for (int kt = 0; kt < nkt; kt++) {
        const bool has = (kt + 1) < nkt;
        const int k0n = (kt + 1) * 32;

        if (has) {
            #pragma unroll
            for (int it = 0; it < 4; it++) {
                int row = prow + 32 * it;
                rP[it] = __ldcs((const float4*)&P[(size_t)row * SEQ + k0n + pc4]);
            }
            rVh = *(const float4*)&Vh[(size_t)vrow * SEQ + k0n + vc8];
            rVl = *(const float4*)&Vl[(size_t)vrow * SEQ + k0n + vc8];
        }

        #pragma unroll
        for (int ks = 0; ks < 2; ks++) {
            uint32_t a[2][4], bh2[4][2], bl2[4][2];
            #pragma unroll
            for (int mm = 0; mm < 2; mm++) ldsm_x4(a[mm], uP + aOff[mm] + ks * 32);
            #pragma unroll
            for (int nn = 0; nn < 4; nn++) ldsm_x2(bh2[nn], uVh + bOff[nn] + ks * 32);
            #pragma unroll
            for (int nn = 0; nn < 4; nn++) ldsm_x2(bl2[nn], uVl + bOff[nn] + ks * 32);
            #pragma unroll
            for (int mm = 0; mm < 2; mm++)
                #pragma unroll
                for (int nn = 0; nn < 4; nn++) {
                    mma_fp16(acc[mm][nn], a[mm], bh2[nn]);
                    mma_fp16(acc[mm][nn], a[mm], bl2[nn]);
                }
        }

        if (has) {
            __syncthreads();
            #pragma unroll
            for (int it = 0; it < 4; it++) {
                int row = prow + 32 * it;
                *(uint2*)&sP[row * 40 + pc4] = make_uint2(
                    pack_h2(__float2half_rn(rP[it].x), __float2half_rn(rP[it].y)),
                    pack_h2(__float2half_rn(rP[it].z), __float2half_rn(rP[it].w)));
            }
            *(float4*)&sVh[vrow * 40 + vc8] = rVh;
            *(float4*)&sVl[vrow * 40 + vc8] = rVl;
            __syncthreads();
        }
    }

    const int rq = lane >> 2, tg = lane & 3;
    #pragma unroll
    for (int mm = 0; mm < 2; mm++) {
        int rloc = warp_m * 32 + mm * 16 + rq;
        #pragma unroll
        for (int nn = 0; nn < 4; nn++) {
            int c = h * DHEAD + warp_n * 32 + nn * 8 + 2 * tg;
            #pragma unroll
            for (int half = 0; half < 2; half++) {
                size_t row = (size_t)b * SEQ + iBase + rloc + half * 8;
                size_t dst = row * INNER + c;
                float c0 = acc[mm][nn][half * 2 + 0];
                float c1 = acc[mm][nn][half * 2 + 1];
                __nv_bfloat16 h0, h1, l0, l1;
                split1(c0, h0, l0); split1(c1, h1, l1);
                *(uint32_t*)&g_oh[dst] = pack_bf2(h0, h1);
                *(uint32_t*)&g_ol[dst] = pack_bf2(l0, l1);
            }
        }
    }
}

// =====================================================================
// launch — kernel launches ONLY; NO device-global symbols referenced here.
// 4th launch (index 3) = Q gemm, lands in the ncu capture window.
// =====================================================================
extern "C" void kernel_launch(void* const* d_in, const int* in_sizes, int n_in,
                              void* d_out, int out_size)
{
    const float* x    = (const float*)d_in[0];
    const float* Wq   = (const float*)d_in[1];
    const float* Wkv  = (const float*)d_in[2];
    const float* pre  = (const float*)d_in[3];
    const float* post = (const float*)d_in[4];
    const float* Wo   = (const float*)d_in[5];
    const float* bo   = (const float*)d_in[6];
    float* out = (float*)d_out;

    k_split_x<<<(int)(X_ELEMS / 256), 256>>>(x);                              // 0
    k_splitw_qkv<<<dim3(DIM * INNER / 256, 3), 256>>>(Wq, Wkv);               // 1
    k_splitw_o<<<INNER * DIM / 256, 256>>>(Wo);                               // 2

    // projections — compile-time specialized (128 regs, 2 blocks/SM)
    k_gemm_hmma<0, 0, DIM, 0, 0>                                              // 3 (ncu)
        <<<dim3(INNER / 128, MTOT / 128), 256>>>(nullptr, nullptr);           // Q
    k_gemm_hmma<1, 1, DIM, 0, 0>
        <<<dim3(INNER / 128, MTOT / 128), 256>>>(nullptr, nullptr);           // K
    k_gemm_hmma<2, 2, DIM, INNER, 2 * INNER>
        <<<dim3(INNER / 128, MTOT / 128), 256>>>(nullptr, nullptr);           // V

    // attention
    k_vt<<<dim3(SEQ / 32, DHEAD / 32, BATCH * NHEAD), 256>>>();
    k_qk_mma<<<dim3(SEQ / 128, SEQ / 128, BATCH * NHEAD), 256>>>();
    k_mix_softmax<<<BATCH * SEQ, 512>>>(pre, post);
    k_av_mma<<<dim3(SEQ / 128, BATCH * NHEAD), 256>>>();   // -> g_oh/g_ol

    // output projection (fp32 + bias to harness out)
    k_gemm_hmma<3, 3, INNER, 0, DIM>
        <<<dim3(DIM / 128, MTOT / 128), 256>>>(out, bo);
}

// round 17
// speedup vs baseline: 1.1110x; 1.0619x over previous
#include <cuda_runtime.h>
#include <cuda_bf16.h>
#include <cuda_fp16.h>
#include <cstddef>
#include <cstdint>

#define BATCH 16
#define SEQ   1024
#define DIM   768
#define NHEAD 12
#define DHEAD 64
#define INNER 768            // NHEAD*DHEAD
#define QK_SCALE 0.125f      // DHEAD^-0.5
#define MTOT (BATCH * SEQ)   // 16384

// ---------------- scratch (device globals; no allocation allowed) ----------------
__device__ float g_kv[(size_t)MTOT * 2 * INNER];                    // 101 MB (V half used)
__device__ float g_at[(size_t)BATCH * NHEAD * SEQ * SEQ];           // 805 MB (S logits fp32)
__device__ __half g_p[(size_t)BATCH * NHEAD * SEQ * SEQ];           // 402 MB (P fp16)
#define QK_ELEMS ((size_t)BATCH * NHEAD * SEQ * DHEAD)              // 12.58M
#define X_ELEMS  ((size_t)MTOT * INNER)                             // 12.58M
// bf16 splits
__device__ __nv_bfloat16 g_xh[X_ELEMS], g_xl[X_ELEMS];
__device__ __nv_bfloat16 g_oh[X_ELEMS], g_ol[X_ELEMS];
__device__ __nv_bfloat16 g_qh[QK_ELEMS], g_ql[QK_ELEMS];
__device__ __nv_bfloat16 g_kh[QK_ELEMS], g_kl[QK_ELEMS];
// V transposed+split [b,h,d,j]  (fp16 for the 2-pass AV)
__device__ __half g_vth[QK_ELEMS], g_vtl[QK_ELEMS];
// transposed+split weights [N][K]
__device__ __nv_bfloat16 g_wqt_h[DIM * INNER], g_wqt_l[DIM * INNER];
__device__ __nv_bfloat16 g_wkt_h[DIM * INNER], g_wkt_l[DIM * INNER];
__device__ __nv_bfloat16 g_wvt_h[DIM * INNER], g_wvt_l[DIM * INNER];
__device__ __nv_bfloat16 g_wot_h[INNER * DIM], g_wot_l[INNER * DIM];

// ---------------- cp.async helpers ----------------
__device__ __forceinline__ void cp16(uint32_t saddr, const void* gptr) {
    asm volatile("cp.async.cg.shared.global [%0], [%1], 16;" :: "r"(saddr), "l"(gptr));
}
__device__ __forceinline__ void cp_commit() { asm volatile("cp.async.commit_group;"); }
__device__ __forceinline__ void cp_wait0()  { asm volatile("cp.async.wait_group 0;"); }
__device__ __forceinline__ void cp_wait1()  { asm volatile("cp.async.wait_group 1;"); }

// ---------------- mma.sync / ldmatrix helpers (baseline PTX) ----------------
__device__ __forceinline__ uint32_t smem_to_u32(const void* p) {
    uint32_t a;
    asm("{ .reg .u64 t; cvta.to.shared.u64 t, %1; cvt.u32.u64 %0, t; }" : "=r"(a) : "l"(p));
    return a;
}
__device__ __forceinline__ void ldsm_x4(uint32_t* r, uint32_t addr) {
    asm volatile("ldmatrix.sync.aligned.m8n8.x4.shared.b16 {%0,%1,%2,%3}, [%4];"
        : "=r"(r[0]), "=r"(r[1]), "=r"(r[2]), "=r"(r[3]) : "r"(addr));
}
__device__ __forceinline__ void ldsm_x2(uint32_t* r, uint32_t addr) {
    asm volatile("ldmatrix.sync.aligned.m8n8.x2.shared.b16 {%0,%1}, [%2];"
        : "=r"(r[0]), "=r"(r[1]) : "r"(addr));
}
__device__ __forceinline__ void mma_bf16(float* c, const uint32_t* a, const uint32_t* b) {
    asm volatile(
        "mma.sync.aligned.m16n8k16.row.col.f32.bf16.bf16.f32 "
        "{%0,%1,%2,%3}, {%4,%5,%6,%7}, {%8,%9}, {%0,%1,%2,%3};"
        : "+f"(c[0]), "+f"(c[1]), "+f"(c[2]), "+f"(c[3])
        : "r"(a[0]), "r"(a[1]), "r"(a[2]), "r"(a[3]), "r"(b[0]), "r"(b[1]));
}
__device__ __forceinline__ void mma_fp16(float* c, const uint32_t* a, const uint32_t* b) {
    asm volatile(
        "mma.sync.aligned.m16n8k16.row.col.f32.f16.f16.f32 "
        "{%0,%1,%2,%3}, {%4,%5,%6,%7}, {%8,%9}, {%0,%1,%2,%3};"
        : "+f"(c[0]), "+f"(c[1]), "+f"(c[2]), "+f"(c[3])
        : "r"(a[0]), "r"(a[1]), "r"(a[2]), "r"(a[3]), "r"(b[0]), "r"(b[1]));
}
__device__ __forceinline__ uint32_t pack_bf2(__nv_bfloat16 a, __nv_bfloat16 b) {
    __nv_bfloat162 t; t.x = a; t.y = b;
    return *(uint32_t*)&t;
}
__device__ __forceinline__ void split1(float v, __nv_bfloat16& h, __nv_bfloat16& l) {
    h = __float2bfloat16(v);
    l = __float2bfloat16(v - __bfloat162float(h));
}
__device__ __forceinline__ void split1h(float v, __half& h, __half& l) {
    h = __float2half_rn(v);
    l = __float2half_rn(v - __half2float(h));
}
__device__ __forceinline__ void stcs_u32(void* p, uint32_t v) {
    asm volatile("st.global.cs.u32 [%0], %1;" :: "l"(p), "r"(v) : "memory");
}

// =====================================================================
// Splitters
// =====================================================================
__global__ __launch_bounds__(256)
void k_split_x(const float* __restrict__ x)
{
    size_t idx = (size_t)blockIdx.x * 256 + threadIdx.x;
    float v = x[idx];
    __nv_bfloat16 h, l; split1(v, h, l);
    g_xh[idx] = h; g_xl[idx] = l;
}

__global__ __launch_bounds__(256)
void k_splitw_qkv(const float* __restrict__ Wq, const float* __restrict__ Wkv)
{
    const int sel = blockIdx.y;
    const float* W = (sel == 0) ? Wq : Wkv;
    const int ldw = (sel == 0) ? INNER : 2 * INNER;
    const int col0 = (sel == 2) ? INNER : 0;

    size_t idx = (size_t)blockIdx.x * 256 + threadIdx.x;   // n*K + k, K=DIM
    int k = (int)(idx % DIM);
    int n = (int)(idx / DIM);
    float v = W[(size_t)k * ldw + col0 + n];
    __nv_bfloat16 h, l; split1(v, h, l);
    __nv_bfloat16* oh = (sel == 0) ? g_wqt_h : (sel == 1) ? g_wkt_h : g_wvt_h;
    __nv_bfloat16* ol = (sel == 0) ? g_wqt_l : (sel == 1) ? g_wkt_l : g_wvt_l;
    oh[idx] = h; ol[idx] = l;
}

__global__ __launch_bounds__(256)
void k_splitw_o(const float* __restrict__ Wo)
{
    size_t idx = (size_t)blockIdx.x * 256 + threadIdx.x;   // n*K + k, K=INNER
    int k = (int)(idx % INNER);
    int n = (int)(idx / INNER);
    float v = Wo[(size_t)k * DIM + n];
    __nv_bfloat16 h, l; split1(v, h, l);
    g_wot_h[idx] = h; g_wot_l[idx] = l;
}

// =====================================================================
// k_vt: V fp32 -> fp16 hi/lo transposed [bh][d][j]
// =====================================================================
__global__ __launch_bounds__(256)
void k_vt()
{
    __shared__ __half th[32][33];
    __shared__ __half tl[32][33];
    const int bh = blockIdx.z;
    const int b = bh / NHEAD, h = bh % NHEAD;
    const int j0 = blockIdx.x * 32, d0 = blockIdx.y * 32;
    const int tx = threadIdx.x & 31, ty = threadIdx.x >> 5;

    __half* oh = g_vth + (size_t)bh * DHEAD * SEQ;
    __half* ol = g_vtl + (size_t)bh * DHEAD * SEQ;

    #pragma unroll
    for (int i = 0; i < 4; i++) {
        int r = ty + i * 8;
        float v = g_kv[((size_t)(b * SEQ + j0 + r)) * (2 * INNER) + INNER + h * DHEAD + d0 + tx];
        __half hh, ll; split1h(v, hh, ll);
        th[r][tx] = hh; tl[r][tx] = ll;
    }
    __syncthreads();
    #pragma unroll
    for (int i = 0; i < 4; i++) {
        int r = ty + i * 8;
        oh[(size_t)(d0 + r) * SEQ + j0 + tx] = th[tx][r];
        ol[(size_t)(d0 + r) * SEQ + j0 + tx] = tl[tx][r];
    }
}

// =====================================================================
// k_gemm_hmma<SELAB, SELC, K, COLOFF, LDC>: compile-time specialized (R15)
// =====================================================================
#define GS_STRIDE 24
#define GS_TILE   (128 * GS_STRIDE)

template<int SELAB, int SELC, int K, int COLOFF, int LDC>
__global__ __launch_bounds__(256)
void k_gemm_hmma(float* __restrict__ outp, const float* __restrict__ bias)
{
    __shared__ __nv_bfloat16 sm[2][4][GS_TILE];

    const __nv_bfloat16* Ah = (SELAB == 3) ? g_oh : g_xh;
    const __nv_bfloat16* Al = (SELAB == 3) ? g_ol : g_xl;
    const __nv_bfloat16* Bh = (SELAB == 0) ? g_wqt_h : (SELAB == 1) ? g_wkt_h
                            : (SELAB == 2) ? g_wvt_h : g_wot_h;
    const __nv_bfloat16* Bl = (SELAB == 0) ? g_wqt_l : (SELAB == 1) ? g_wkt_l
                            : (SELAB == 2) ? g_wvt_l : g_wot_l;

    const int tid = threadIdx.x;
    const int lane = tid & 31, wid = tid >> 5;
    const int warp_m = wid >> 2, warp_n = wid & 3;
    const int iBase = blockIdx.y * 128, nBase = blockIdx.x * 128;

    float acc[4][4][4];
    #pragma unroll
    for (int m = 0; m < 4; m++)
        #pragma unroll
        for (int n = 0; n < 4; n++)
            #pragma unroll
            for (int k = 0; k < 4; k++) acc[m][n][k] = 0.f;

    const uint32_t uBase = smem_to_u32(sm);

    uint32_t aOff[4], bOff[4];
    #pragma unroll
    for (int mm = 0; mm < 4; mm++)
        aOff[mm] = (uint32_t)(((warp_m * 64 + mm * 16 + (lane & 15)) * GS_STRIDE
                               + (lane >> 4) * 8) * 2);
    #pragma unroll
    for (int nn = 0; nn < 4; nn++)
        bOff[nn] = (uint32_t)(((warp_n * 32 + nn * 8 + (lane & 7)) * GS_STRIDE
                               + ((lane >> 3) & 1) * 8) * 2);

    const __nv_bfloat16* pAh = Ah + (size_t)iBase * K;
    const __nv_bfloat16* pAl = Al + (size_t)iBase * K;
    const __nv_bfloat16* pBh = Bh + (size_t)nBase * K;
    const __nv_bfloat16* pBl = Bl + (size_t)nBase * K;

    const int crow = tid >> 1, chalf = tid & 1;
    const uint32_t cdst = (uint32_t)(crow * GS_STRIDE + chalf * 8) * 2;
    const size_t  csrc = (size_t)crow * K + chalf * 8;

    auto issue = [&](int stage, int k0) {
        uint32_t sb = uBase + (uint32_t)(stage * 4) * (GS_TILE * 2);
        cp16(sb + 0 * (GS_TILE * 2) + cdst, pAh + csrc + k0);
        cp16(sb + 1 * (GS_TILE * 2) + cdst, pAl + csrc + k0);
        cp16(sb + 2 * (GS_TILE * 2) + cdst, pBh + csrc + k0);
        cp16(sb + 3 * (GS_TILE * 2) + cdst, pBl + csrc + k0);
    };

    const int nkt = K / 16;
    issue(0, 0); cp_commit();

    for (int kt = 0; kt < nkt; kt++) {
        const int cur = kt & 1, nxt = cur ^ 1;
        const bool has = (kt + 1) < nkt;

        if (has) { issue(nxt, (kt + 1) * 16); cp_commit(); cp_wait1(); }
        else     { cp_wait0(); }
        __syncthreads();

        const uint32_t sb = uBase + (uint32_t)(cur * 4) * (GS_TILE * 2);
        #pragma unroll
        for (int p = 0; p < 3; p++) {
            uint32_t uA = sb + (uint32_t)(p == 2 ? 1 : 0) * (GS_TILE * 2);
            uint32_t uB = sb + (uint32_t)(p == 1 ? 3 : 2) * (GS_TILE * 2);
            uint32_t a[4][4], b[4][2];
            #pragma unroll
            for (int mm = 0; mm < 4; mm++) ldsm_x4(a[mm], uA + aOff[mm]);
            #pragma unroll
            for (int nn = 0; nn < 4; nn++) ldsm_x2(b[nn], uB + bOff[nn]);
            #pragma unroll
            for (int mm = 0; mm < 4; mm++)
                #pragma unroll
                for (int nn = 0; nn < 4; nn++)
                    mma_bf16(acc[mm][nn], a[mm], b[nn]);
        }
        __syncthreads();
    }

    const int rq = lane >> 2, tg = lane & 3;
    if (SELC <= 1) {
        __nv_bfloat16* dh = (SELC == 0) ? g_qh : g_kh;
        __nv_bfloat16* dl = (SELC == 0) ? g_ql : g_kl;
        #pragma unroll
        for (int mm = 0; mm < 4; mm++) {
            int r0 = iBase + warp_m * 64 + mm * 16 + rq;
            #pragma unroll
            for (int nn = 0; nn < 4; nn++) {
                int c = nBase + warp_n * 32 + nn * 8 + 2 * tg;
                int h = c >> 6, d = c & (DHEAD - 1);
                #pragma unroll
                for (int half = 0; half < 2; half++) {
                    int row = r0 + half * 8;
                    int b = row >> 10, i = row & (SEQ - 1);
                    size_t dst = ((size_t)(b * NHEAD + h) * SEQ + i) * DHEAD + d;
                    float c0 = acc[mm][nn][half * 2 + 0];
                    float c1 = acc[mm][nn][half * 2 + 1];
                    __nv_bfloat16 h0, h1, l0, l1;
                    split1(c0, h0, l0); split1(c1, h1, l1);
                    *(uint32_t*)&dh[dst] = pack_bf2(h0, h1);
                    *(uint32_t*)&dl[dst] = pack_bf2(l0, l1);
                }
            }
        }
    } else {
        float* C = (SELC == 2) ? g_kv : outp;
        #pragma unroll
        for (int mm = 0; mm < 4; mm++) {
            int r0 = iBase + warp_m * 64 + mm * 16 + rq;
            #pragma unroll
            for (int nn = 0; nn < 4; nn++) {
                int c = nBase + warp_n * 32 + nn * 8 + 2 * tg;
                float bx = (SELC == 3) ? bias[c] : 0.f;
                float by = (SELC == 3) ? bias[c + 1] : 0.f;
                float2 v0 = { acc[mm][nn][0] + bx, acc[mm][nn][1] + by };
                float2 v1 = { acc[mm][nn][2] + bx, acc[mm][nn][3] + by };
                *(float2*)&C[(size_t)r0 * LDC + COLOFF + c] = v0;
                *(float2*)&C[(size_t)(r0 + 8) * LDC + COLOFF + c] = v1;
            }
        }
    }
}

// =====================================================================
// QK^T via mma.sync bf16x3; streaming stores on S (fp32)
// =====================================================================
__global__ __launch_bounds__(256)
void k_qk_mma()
{
    __shared__ __nv_bfloat16 sA[128 * 72];
    __shared__ __nv_bfloat16 sB[128 * 72];

    const int tid = threadIdx.x;
    const int lane = tid & 31, wid = tid >> 5;
    const int warp_m = wid >> 2, warp_n = wid & 3;
    const int bh = blockIdx.z;
    const int iBase = blockIdx.y * 128, jBase = blockIdx.x * 128;

    const __nv_bfloat16* Qh = g_qh + ((size_t)bh * SEQ + iBase) * DHEAD;
    const __nv_bfloat16* Ql = g_ql + ((size_t)bh * SEQ + iBase) * DHEAD;
    const __nv_bfloat16* Kh = g_kh + ((size_t)bh * SEQ + jBase) * DHEAD;
    const __nv_bfloat16* Kl = g_kl + ((size_t)bh * SEQ + jBase) * DHEAD;

    float acc[4][4][4];
    #pragma unroll
    for (int m = 0; m < 4; m++)
        #pragma unroll
        for (int n = 0; n < 4; n++)
            #pragma unroll
            for (int k = 0; k < 4; k++) acc[m][n][k] = 0.f;

    const uint32_t sA_u = smem_to_u32(sA), sB_u = smem_to_u32(sB);

    uint32_t aOff[4], bOff[4];
    #pragma unroll
    for (int mm = 0; mm < 4; mm++)
        aOff[mm] = (uint32_t)(((warp_m * 64 + mm * 16 + (lane & 15)) * 72
                               + (lane >> 4) * 8) * 2);
    #pragma unroll
    for (int nn = 0; nn < 4; nn++)
        bOff[nn] = (uint32_t)(((warp_n * 32 + nn * 8 + (lane & 7)) * 72
                               + ((lane >> 3) & 1) * 8) * 2);

    auto load_tile = [&](__nv_bfloat16* dst, const __nv_bfloat16* src) {
        #pragma unroll
        for (int it = 0; it < 4; it++) {
            int idx = tid + 256 * it;
            int row = idx >> 3, c8 = (idx & 7) * 8;
            *(float4*)&dst[row * 72 + c8] = *(const float4*)&src[(size_t)row * DHEAD + c8];
        }
    };
    auto pass = [&]() {
        #pragma unroll
        for (int ks = 0; ks < 4; ks++) {
            uint32_t a[4][4], b[4][2];
            #pragma unroll
            for (int mm = 0; mm < 4; mm++) ldsm_x4(a[mm], sA_u + aOff[mm] + ks * 32);
            #pragma unroll
            for (int nn = 0; nn < 4; nn++) ldsm_x2(b[nn], sB_u + bOff[nn] + ks * 32);
            #pragma unroll
            for (int mm = 0; mm < 4; mm++)
                #pragma unroll
                for (int nn = 0; nn < 4; nn++)
                    mma_bf16(acc[mm][nn], a[mm], b[nn]);
        }
    };

    load_tile(sA, Ql); load_tile(sB, Kh);
    __syncthreads();
    pass();
    __syncthreads();
    load_tile(sA, Qh);
    __syncthreads();
    pass();
    __syncthreads();
    load_tile(sB, Kl);
    __syncthreads();
    pass();

    float* S = g_at + (size_t)bh * SEQ * SEQ;
    const int g = lane >> 2, tg = lane & 3;
    #pragma unroll
    for (int mm = 0; mm < 4; mm++) {
        int r0 = iBase + warp_m * 64 + mm * 16 + g;
        #pragma unroll
        for (int nn = 0; nn < 4; nn++) {
            int c = jBase + warp_n * 32 + nn * 8 + 2 * tg;
            float2 v0 = { acc[mm][nn][0] * QK_SCALE, acc[mm][nn][1] * QK_SCALE };
            float2 v1 = { acc[mm][nn][2] * QK_SCALE, acc[mm][nn][3] * QK_SCALE };
            __stcs((float2*)&S[(size_t)r0 * SEQ + c], v0);
            __stcs((float2*)&S[(size_t)(r0 + 8) * SEQ + c], v1);
        }
    }
}

// =====================================================================
// Fused talking-heads (no max pass, incremental premix).
// Reads S fp32 from g_at; WRITES P fp16 to g_p.
// =====================================================================
__global__ __launch_bounds__(512)
void k_mix_softmax(const float* __restrict__ pre, const float* __restrict__ post)
{
    __shared__ float sp[NHEAD * NHEAD];
    __shared__ float sq[NHEAD * NHEAD];
    __shared__ float red[NHEAD][16];
    __shared__ float bc[NHEAD];

    const int tid = threadIdx.x;
    const int lane = tid & 31, wid = tid >> 5;

    if (tid < NHEAD * NHEAD) { sp[tid] = pre[tid]; sq[tid] = post[tid]; }
    __syncthreads();

    const int b = blockIdx.x >> 10;
    const int i = blockIdx.x & (SEQ - 1);
    const float* baseS = g_at + (size_t)b * NHEAD * SEQ * SEQ + (size_t)i * SEQ + tid * 2;
    __half* baseP = g_p + (size_t)b * NHEAD * SEQ * SEQ + (size_t)i * SEQ + tid * 2;

    float2 t2[NHEAD];
    #pragma unroll
    for (int g = 0; g < NHEAD; g++) { t2[g].x = 0.f; t2[g].y = 0.f; }
    #pragma unroll
    for (int h = 0; h < NHEAD; h++) {
        float2 s = __ldcs((const float2*)&baseS[(size_t)h * SEQ * SEQ]);
        #pragma unroll
        for (int g = 0; g < NHEAD; g++) {
            float w = sp[h * NHEAD + g];
            t2[g].x = fmaf(s.x, w, t2[g].x);
            t2[g].y = fmaf(s.y, w, t2[g].y);
        }
    }

    #pragma unroll
    for (int g = 0; g < NHEAD; g++) {
        t2[g].x = __expf(t2[g].x);
        t2[g].y = __expf(t2[g].y);
    }

    #pragma unroll
    for (int g = 0; g < NHEAD; g++) {
        float v = t2[g].x + t2[g].y;
        #pragma unroll
        for (int o = 16; o; o >>= 1) v += __shfl_xor_sync(0xffffffffu, v, o);
        if (lane == 0) red[g][wid] = v;
    }
    __syncthreads();
    if (tid < NHEAD) {
        float v = red[tid][0];
        #pragma unroll
        for (int k = 1; k < 16; k++) v += red[tid][k];
        bc[tid] = 1.f / v;
    }
    __syncthreads();

    #pragma unroll
    for (int g = 0; g < NHEAD; g++) { t2[g].x *= bc[g]; t2[g].y *= bc[g]; }

    #pragma unroll
    for (int g2 = 0; g2 < NHEAD; g2++) {
        float ux = 0.f, uy = 0.f;
        #pragma unroll
        for (int g = 0; g < NHEAD; g++) {
            float w = sq[g * NHEAD + g2];
            ux = fmaf(t2[g].x, w, ux);
            uy = fmaf(t2[g].y, w, uy);
        }
        __half2 hv = __floats2half2_rn(ux, uy);
        stcs_u32(&baseP[(size_t)g2 * SEQ * SEQ], *(uint32_t*)&hv);
    }
}

// =====================================================================
// k_av_mma: O = P @ V per (b,h), fp16 2-pass, full cp.async pipeline.
// P stage = 128 rows x 32 halves = 512 x 16B chunks (2/thread):
//   chunk = tid and tid+256; row = chunk>>2; seg = (chunk&3)*8.   (R16 bug fixed)
// V stages = 64 rows x 32 halves = 256 chunks each (1/thread).
// =====================================================================
#define AV_VHOFF (128 * 40)
#define AV_VLOFF (128 * 40 + 64 * 40)
#define AV_STAGE (128 * 40 + 2 * 64 * 40)   // halves per stage = 10240

__global__ __launch_bounds__(256)
void k_av_mma()
{
    __shared__ __half sm[2][AV_STAGE];

    const int tid = threadIdx.x;
    const int lane = tid & 31, wid = tid >> 5;
    const int warp_m = wid >> 1, warp_n = wid & 1;   // 4m x 2n
    const int bh = blockIdx.y;
    const int b = bh / NHEAD, h = bh % NHEAD;
    const int iBase = blockIdx.x * 128;

    const __half* P  = g_p  + (size_t)bh * SEQ * SEQ + (size_t)iBase * SEQ;
    const __half* Vh = g_vth + (size_t)bh * DHEAD * SEQ;
    const __half* Vl = g_vtl + (size_t)bh * DHEAD * SEQ;

    float acc[2][4][4];
    #pragma unroll
    for (int m = 0; m < 2; m++)
        #pragma unroll
        for (int n = 0; n < 4; n++)
            #pragma unroll
            for (int k = 0; k < 4; k++) acc[m][n][k] = 0.f;

    const uint32_t uBase = smem_to_u32(sm);

    uint32_t aOff[2], bOff[4];
    #pragma unroll
    for (int mm = 0; mm < 2; mm++)
        aOff[mm] = (uint32_t)(((warp_m * 32 + mm * 16 + (lane & 15)) * 40
                               + (lane >> 4) * 8) * 2);
    #pragma unroll
    for (int nn = 0; nn < 4; nn++)
        bOff[nn] = (uint32_t)(((warp_n * 32 + nn * 8 + (lane & 7)) * 40
                               + ((lane >> 3) & 1) * 8) * 2);

    // CORRECTED cp.async coordinates (4 chunks of 16B per 32-half row):
    const int pr0 = tid >> 2,           ps0 = (tid & 3) * 8;  // rows 0..63
    const int pr1 = (tid + 256) >> 2,   ps1 = ps0;            // rows 64..127
    const int vrow = tid >> 2,          vseg = (tid & 3) * 8;

    auto issue = [&](int stage, int k0) {
        uint32_t sb = uBase + (uint32_t)stage * (AV_STAGE * 2);
        cp16(sb + (uint32_t)(pr0 * 40 + ps0) * 2, P + (size_t)pr0 * SEQ + k0 + ps0);
        cp16(sb + (uint32_t)(pr1 * 40 + ps1) * 2, P + (size_t)pr1 * SEQ + k0 + ps1);
        cp16(sb + (uint32_t)(AV_VHOFF + vrow * 40 + vseg) * 2, Vh + (size_t)vrow * SEQ + k0 + vseg);
        cp16(sb + (uint32_t)(AV_VLOFF + vrow * 40 + vseg) * 2, Vl + (size_t)vrow * SEQ + k0 + vseg);
    };

    const int nkt = SEQ / 32;   // 32
    issue(0, 0); cp_commit();

    for (int kt = 0; kt < nkt; kt++) {
        const int cur = kt & 1, nxt = cur ^ 1;
        const bool has = (kt + 1) < nkt;

        if (has) { issue(nxt, (kt + 1) * 32); cp_commit(); cp_wait1(); }
        else     { cp_wait0(); }
        __syncthreads();

        const uint32_t sb = uBase + (uint32_t)cur * (AV_STAGE * 2);
        #pragma unroll
        for (int ks = 0; ks < 2; ks++) {
            uint32_t a[2][4], bh2[4][2], bl2[4][2];
            #pragma unroll
            for (int mm = 0; mm < 2; mm++) ldsm_x4(a[mm], sb + aOff[mm] + ks * 32);
            #pragma unroll
            for (int nn = 0; nn < 4; nn++) ldsm_x2(bh2[nn], sb + AV_VHOFF * 2 + bOff[nn] + ks * 32);
            #pragma unroll
            for (int nn = 0; nn < 4; nn++) ldsm_x2(bl2[nn], sb + AV_VLOFF * 2 + bOff[nn] + ks * 32);
            #pragma unroll
            for (int mm = 0; mm < 2; mm++)
                #pragma unroll
                for (int nn = 0; nn < 4; nn++) {
                    mma_fp16(acc[mm][nn], a[mm], bh2[nn]);
                    mma_fp16(acc[mm][nn], a[mm], bl2[nn]);
                }
        }
        __syncthreads();
    }

    const int rq = lane >> 2, tg = lane & 3;
    #pragma unroll
    for (int mm = 0; mm < 2; mm++) {
        int rloc = warp_m * 32 + mm * 16 + rq;
        #pragma unroll
        for (int nn = 0; nn < 4; nn++) {
            int c = h * DHEAD + warp_n * 32 + nn * 8 + 2 * tg;
            #pragma unroll
            for (int half = 0; half < 2; half++) {
                size_t row = (size_t)b * SEQ + iBase + rloc + half * 8;
                size_t dst = row * INNER + c;
                float c0 = acc[mm][nn][half * 2 + 0];
                float c1 = acc[mm][nn][half * 2 + 1];
                __nv_bfloat16 h0, h1, l0, l1;
                split1(c0, h0, l0); split1(c1, h1, l1);
                *(uint32_t*)&g_oh[dst] = pack_bf2(h0, h1);
                *(uint32_t*)&g_ol[dst] = pack_bf2(l0, l1);
            }
        }
    }
}

// =====================================================================
// launch — kernel launches ONLY; NO device-global symbols referenced here.
// =====================================================================
extern "C" void kernel_launch(void* const* d_in, const int* in_sizes, int n_in,
                              void* d_out, int out_size)
{
    const float* x    = (const float*)d_in[0];
    const float* Wq   = (const float*)d_in[1];
    const float* Wkv  = (const float*)d_in[2];
    const float* pre  = (const float*)d_in[3];
    const float* post = (const float*)d_in[4];
    const float* Wo   = (const float*)d_in[5];
    const float* bo   = (const float*)d_in[6];
    float* out = (float*)d_out;

    k_split_x<<<(int)(X_ELEMS / 256), 256>>>(x);
    k_splitw_qkv<<<dim3(DIM * INNER / 256, 3), 256>>>(Wq, Wkv);
    k_splitw_o<<<INNER * DIM / 256, 256>>>(Wo);

    // projections — compile-time specialized
    k_gemm_hmma<0, 0, DIM, 0, 0>
        <<<dim3(INNER / 128, MTOT / 128), 256>>>(nullptr, nullptr);           // Q
    k_gemm_hmma<1, 1, DIM, 0, 0>
        <<<dim3(INNER / 128, MTOT / 128), 256>>>(nullptr, nullptr);           // K
    k_gemm_hmma<2, 2, DIM, INNER, 2 * INNER>
        <<<dim3(INNER / 128, MTOT / 128), 256>>>(nullptr, nullptr);           // V

    // attention
    k_vt<<<dim3(SEQ / 32, DHEAD / 32, BATCH * NHEAD), 256>>>();
    k_qk_mma<<<dim3(SEQ / 128, SEQ / 128, BATCH * NHEAD), 256>>>();
    k_mix_softmax<<<BATCH * SEQ, 512>>>(pre, post);       // -> g_p (fp16)
    k_av_mma<<<dim3(SEQ / 128, BATCH * NHEAD), 256>>>();  // -> g_oh/g_ol

    // output projection (fp32 + bias to harness out)
    k_gemm_hmma<3, 3, INNER, 0, DIM>
        <<<dim3(DIM / 128, MTOT / 128), 256>>>(out, bo);
}